// round 1
// baseline (speedup 1.0000x reference)
#include <cuda_runtime.h>

#define DIMC   1024
#define NHEAD  16
#define HDIM   64
#define BATCH  4
#define SEQ    2048
#define MTOT   (BATCH*SEQ)   /* 8192 */
#define NQKV   (3*DIMC)      /* 3072 */

// Scratch: qkv laid out [3][B][H][SEQ][HDIM]; attn out laid out [B*SEQ][DIMC]
__device__ float g_qkv[(size_t)3 * BATCH * NHEAD * SEQ * HDIM];   // 96 MB
__device__ float g_attn[(size_t)MTOT * DIMC];                     // 32 MB

// ---------------------------------------------------------------------------
// GEMM 1: qkv = x @ W_qkv + b_qkv, epilogue scatters into [3][B][H][S][D]
// A: [MTOT, 1024] row-major, B: [1024, 3072] row-major
// 128x128 tile, BK=8, 256 threads, 8x8 per-thread microtile
// ---------------------------------------------------------------------------
__global__ __launch_bounds__(256)
void gemm_qkv_kernel(const float* __restrict__ A, const float* __restrict__ B,
                     const float* __restrict__ bias)
{
    const int K = DIMC, N = NQKV;
    __shared__ float As[8][128];
    __shared__ float Bs[8][128];

    const int tid  = threadIdx.x;
    const int tr   = tid >> 4;          // 0..15
    const int tc   = tid & 15;          // 0..15
    const int rowA = tid >> 1;          // 0..127
    const int colA = (tid & 1) << 2;    // 0 or 4
    const int rowB = tid >> 5;          // 0..7
    const int colB = (tid & 31) << 2;   // 0..124

    const float* Ab = A + (size_t)(blockIdx.y * 128) * K;
    const float* Bb = B + blockIdx.x * 128;

    float acc[8][8] = {};

    for (int kb = 0; kb < K; kb += 8) {
        float4 a4 = *(const float4*)(Ab + (size_t)rowA * K + kb + colA);
        As[colA + 0][rowA] = a4.x;
        As[colA + 1][rowA] = a4.y;
        As[colA + 2][rowA] = a4.z;
        As[colA + 3][rowA] = a4.w;
        *(float4*)&Bs[rowB][colB] = *(const float4*)(Bb + (size_t)(kb + rowB) * N + colB);
        __syncthreads();
        #pragma unroll
        for (int k = 0; k < 8; k++) {
            float rm[8], rn[8];
            *(float4*)(rm + 0) = *(const float4*)&As[k][tr * 8 + 0];
            *(float4*)(rm + 4) = *(const float4*)&As[k][tr * 8 + 4];
            *(float4*)(rn + 0) = *(const float4*)&Bs[k][tc * 8 + 0];
            *(float4*)(rn + 4) = *(const float4*)&Bs[k][tc * 8 + 4];
            #pragma unroll
            for (int i = 0; i < 8; i++)
                #pragma unroll
                for (int j = 0; j < 8; j++)
                    acc[i][j] += rm[i] * rn[j];
        }
        __syncthreads();
    }

    // Epilogue: scatter into [3][B][H][S][D]
    #pragma unroll
    for (int i = 0; i < 8; i++) {
        const int m = blockIdx.y * 128 + tr * 8 + i;
        const int b = m >> 11;        // /2048
        const int s = m & 2047;
        #pragma unroll
        for (int j = 0; j < 8; j++) {
            const int n = blockIdx.x * 128 + tc * 8 + j;
            const float v = acc[i][j] + bias[n];
            const int t = n >> 10;          // 0=q 1=k 2=v
            const int h = (n >> 6) & 15;
            const int d = n & 63;
            g_qkv[((((size_t)t * BATCH + b) * NHEAD + h) * SEQ + s) * HDIM + d] = v;
        }
    }
}

// ---------------------------------------------------------------------------
// Flash attention: per block one (b,h) and a 64-query tile; streams 64-key
// tiles with online softmax. 256 threads as 16x16, 4x4 microtiles.
// smem: Qs[64][64], KPs[64][64] (K^T, reused for P), Vs[64][64] = 48 KB.
// ---------------------------------------------------------------------------
__global__ __launch_bounds__(256)
void flash_kernel()
{
    __shared__ float Qs[64 * 64];
    __shared__ float KPs[64 * 64];
    __shared__ float Vs[64 * 64];

    const int tid = threadIdx.x;
    const int ty  = tid >> 4;       // 0..15
    const int tx  = tid & 15;       // 0..15
    const int r0  = ty * 4;
    const int c0  = tx * 4;

    const int bh = blockIdx.y;
    const int b  = bh >> 4;
    const int h  = bh & 15;
    const int q0 = blockIdx.x * 64;

    const float* Qg = g_qkv + (((size_t)0 * BATCH + b) * NHEAD + h) * SEQ * HDIM;
    const float* Kg = g_qkv + (((size_t)1 * BATCH + b) * NHEAD + h) * SEQ * HDIM;
    const float* Vg = g_qkv + (((size_t)2 * BATCH + b) * NHEAD + h) * SEQ * HDIM;

    // Load Q tile (64x64), direct layout
    {
        int idx = tid;
        #pragma unroll
        for (int it = 0; it < 4; it++, idx += 256) {
            const int r = idx >> 4;
            const int c = (idx & 15) << 2;
            *(float4*)&Qs[r * 64 + c] = *(const float4*)(Qg + (size_t)(q0 + r) * HDIM + c);
        }
    }

    float m_i[4], l_i[4], o[4][4] = {};
    #pragma unroll
    for (int i = 0; i < 4; i++) { m_i[i] = -1e30f; l_i[i] = 0.0f; }
    const float scale = 0.125f;   // 1/sqrt(64)

    for (int kt = 0; kt < SEQ; kt += 64) {
        __syncthreads();   // protect KPs/Vs from previous iteration (also covers Qs on iter 0)
        // Load K (transposed -> KPs[k][c]) and V (direct -> Vs[k][d])
        {
            int idx = tid;
            #pragma unroll
            for (int it = 0; it < 4; it++, idx += 256) {
                const int r = idx >> 4;          // seq within tile
                const int c = (idx & 15) << 2;   // d
                float4 kv = *(const float4*)(Kg + (size_t)(kt + r) * HDIM + c);
                KPs[(c + 0) * 64 + r] = kv.x;
                KPs[(c + 1) * 64 + r] = kv.y;
                KPs[(c + 2) * 64 + r] = kv.z;
                KPs[(c + 3) * 64 + r] = kv.w;
                *(float4*)&Vs[r * 64 + c] = *(const float4*)(Vg + (size_t)(kt + r) * HDIM + c);
            }
        }
        __syncthreads();

        // S = Q @ K^T  (4x4 per thread)
        float s[4][4] = {};
        #pragma unroll 4
        for (int k = 0; k < 64; k += 4) {
            float qv[4][4];
            #pragma unroll
            for (int i = 0; i < 4; i++)
                *(float4*)qv[i] = *(const float4*)&Qs[(r0 + i) * 64 + k];
            #pragma unroll
            for (int kk = 0; kk < 4; kk++) {
                float kv[4];
                *(float4*)kv = *(const float4*)&KPs[(k + kk) * 64 + c0];
                #pragma unroll
                for (int i = 0; i < 4; i++)
                    #pragma unroll
                    for (int j = 0; j < 4; j++)
                        s[i][j] += qv[i][kk] * kv[j];
            }
        }

        // Online softmax stats (row groups = 16 consecutive lanes; shuffle over bits 0..3)
        float alpha[4];
        #pragma unroll
        for (int i = 0; i < 4; i++) {
            float mx = -1e30f;
            #pragma unroll
            for (int j = 0; j < 4; j++) { s[i][j] *= scale; mx = fmaxf(mx, s[i][j]); }
            #pragma unroll
            for (int off = 1; off < 16; off <<= 1)
                mx = fmaxf(mx, __shfl_xor_sync(0xffffffffu, mx, off));
            const float newm = fmaxf(m_i[i], mx);
            alpha[i] = __expf(m_i[i] - newm);
            float sum = 0.0f;
            #pragma unroll
            for (int j = 0; j < 4; j++) { s[i][j] = __expf(s[i][j] - newm); sum += s[i][j]; }
            #pragma unroll
            for (int off = 1; off < 16; off <<= 1)
                sum += __shfl_xor_sync(0xffffffffu, sum, off);
            l_i[i] = l_i[i] * alpha[i] + sum;
            m_i[i] = newm;
        }

        __syncthreads();   // all threads done reading K from KPs
        // Write P into KPs buffer: KPs[r][k]
        #pragma unroll
        for (int i = 0; i < 4; i++)
            *(float4*)&KPs[(r0 + i) * 64 + c0] =
                make_float4(s[i][0], s[i][1], s[i][2], s[i][3]);
        __syncthreads();

        // O = O*alpha + P @ V   (cols of O are d-dims = c0+j)
        #pragma unroll
        for (int i = 0; i < 4; i++)
            #pragma unroll
            for (int j = 0; j < 4; j++)
                o[i][j] *= alpha[i];
        #pragma unroll 4
        for (int k = 0; k < 64; k += 4) {
            float pv[4][4];
            #pragma unroll
            for (int i = 0; i < 4; i++)
                *(float4*)pv[i] = *(const float4*)&KPs[(r0 + i) * 64 + k];
            #pragma unroll
            for (int kk = 0; kk < 4; kk++) {
                float vv[4];
                *(float4*)vv = *(const float4*)&Vs[(k + kk) * 64 + c0];
                #pragma unroll
                for (int i = 0; i < 4; i++)
                    #pragma unroll
                    for (int j = 0; j < 4; j++)
                        o[i][j] += pv[i][kk] * vv[j];
            }
        }
    }

    // Epilogue: normalize and write [B, S, H*D] (row-major [MTOT, DIMC])
    #pragma unroll
    for (int i = 0; i < 4; i++) {
        const float inv = 1.0f / l_i[i];
        const int row = q0 + r0 + i;
        float4 res = make_float4(o[i][0] * inv, o[i][1] * inv, o[i][2] * inv, o[i][3] * inv);
        *(float4*)&g_attn[((size_t)(b * SEQ + row)) * DIMC + h * HDIM + c0] = res;
    }
}

// ---------------------------------------------------------------------------
// GEMM 2: out = attn @ W_proj + b_proj
// A: [MTOT, 1024] (g_attn), B: [1024, 1024], out row-major [MTOT, 1024]
// ---------------------------------------------------------------------------
__global__ __launch_bounds__(256)
void gemm_proj_kernel(const float* __restrict__ B, const float* __restrict__ bias,
                      float* __restrict__ out)
{
    const int K = DIMC, N = DIMC;
    __shared__ float As[8][128];
    __shared__ float Bs[8][128];

    const int tid  = threadIdx.x;
    const int tr   = tid >> 4;
    const int tc   = tid & 15;
    const int rowA = tid >> 1;
    const int colA = (tid & 1) << 2;
    const int rowB = tid >> 5;
    const int colB = (tid & 31) << 2;

    const float* Ab = g_attn + (size_t)(blockIdx.y * 128) * K;
    const float* Bb = B + blockIdx.x * 128;

    float acc[8][8] = {};

    for (int kb = 0; kb < K; kb += 8) {
        float4 a4 = *(const float4*)(Ab + (size_t)rowA * K + kb + colA);
        As[colA + 0][rowA] = a4.x;
        As[colA + 1][rowA] = a4.y;
        As[colA + 2][rowA] = a4.z;
        As[colA + 3][rowA] = a4.w;
        *(float4*)&Bs[rowB][colB] = *(const float4*)(Bb + (size_t)(kb + rowB) * N + colB);
        __syncthreads();
        #pragma unroll
        for (int k = 0; k < 8; k++) {
            float rm[8], rn[8];
            *(float4*)(rm + 0) = *(const float4*)&As[k][tr * 8 + 0];
            *(float4*)(rm + 4) = *(const float4*)&As[k][tr * 8 + 4];
            *(float4*)(rn + 0) = *(const float4*)&Bs[k][tc * 8 + 0];
            *(float4*)(rn + 4) = *(const float4*)&Bs[k][tc * 8 + 4];
            #pragma unroll
            for (int i = 0; i < 8; i++)
                #pragma unroll
                for (int j = 0; j < 8; j++)
                    acc[i][j] += rm[i] * rn[j];
        }
        __syncthreads();
    }

    #pragma unroll
    for (int i = 0; i < 8; i++) {
        const int m = blockIdx.y * 128 + tr * 8 + i;
        const int nb = blockIdx.x * 128 + tc * 8;
        float4 v0 = make_float4(acc[i][0] + bias[nb + 0], acc[i][1] + bias[nb + 1],
                                acc[i][2] + bias[nb + 2], acc[i][3] + bias[nb + 3]);
        float4 v1 = make_float4(acc[i][4] + bias[nb + 4], acc[i][5] + bias[nb + 5],
                                acc[i][6] + bias[nb + 6], acc[i][7] + bias[nb + 7]);
        *(float4*)&out[(size_t)m * N + nb + 0] = v0;
        *(float4*)&out[(size_t)m * N + nb + 4] = v1;
    }
}

// ---------------------------------------------------------------------------
extern "C" void kernel_launch(void* const* d_in, const int* in_sizes, int n_in,
                              void* d_out, int out_size)
{
    const float* x     = (const float*)d_in[0];
    const float* Wqkv  = (const float*)d_in[1];
    const float* bqkv  = (const float*)d_in[2];
    const float* Wproj = (const float*)d_in[3];
    const float* bproj = (const float*)d_in[4];
    float* out = (float*)d_out;

    dim3 g1(NQKV / 128, MTOT / 128);   // (24, 64)
    gemm_qkv_kernel<<<g1, 256>>>(x, Wqkv, bqkv);

    dim3 g2(SEQ / 64, BATCH * NHEAD);  // (32, 64)
    flash_kernel<<<g2, 256>>>();

    dim3 g3(DIMC / 128, MTOT / 128);   // (8, 64)
    gemm_proj_kernel<<<g3, 256>>>(Wproj, bproj, out);
}

// round 2
// speedup vs baseline: 3.2524x; 3.2524x over previous
#include <cuda_runtime.h>

#define DIMC 1024
#define NHEAD 16
#define HDIM 64
#define BATCH 4
#define SEQ 2048
#define MTOT (BATCH*SEQ)
#define NQKV (3*DIMC)

__device__ float g_qkv[(size_t)3*BATCH*NHEAD*SEQ*HDIM];   // [3][B][H][S][D]
__device__ float g_attn[(size_t)MTOT*DIMC];               // [B*S][C]

__device__ __forceinline__ unsigned f2tf(float x){
    unsigned r; asm("cvt.rna.tf32.f32 %0,%1;" : "=r"(r) : "f"(x)); return r;
}

__device__ __forceinline__ void mma8(float* c, const unsigned* a, const unsigned* b){
    asm volatile(
      "mma.sync.aligned.m16n8k8.row.col.f32.tf32.tf32.f32 "
      "{%0,%1,%2,%3},{%4,%5,%6,%7},{%8,%9},{%0,%1,%2,%3};\n"
      : "+f"(c[0]),"+f"(c[1]),"+f"(c[2]),"+f"(c[3])
      : "r"(a[0]),"r"(a[1]),"r"(a[2]),"r"(a[3]),"r"(b[0]),"r"(b[1]));
}

// ---------------------------------------------------------------------------
// Tensor-core GEMM: C = A[M,1024] @ B[1024,N] + bias
// 128x128x16 tiles, double-buffered, tf32 stored in smem.
// As: [k][m] stride 136 (bank = 8k+m  -> conflict-free frags)
// Bs: [k][n] stride 136
// SCATTER=true: epilogue scatters into g_qkv [3][B][H][S][D]
// SCATTER=false: A is ignored, reads g_attn, writes out + bias
// ---------------------------------------------------------------------------
#define ASTR 136
#define BSTR 136

template<int N, bool SCATTER>
__global__ __launch_bounds__(256)
void gemm_mma(const float* __restrict__ A, const float* __restrict__ B,
              const float* __restrict__ bias, float* __restrict__ out)
{
    __shared__ unsigned As[2][16*ASTR];
    __shared__ unsigned Bs[2][16*BSTR];
    const int tid=threadIdx.x, lane=tid&31, warp=tid>>5;
    const int g=lane>>2, tg=lane&3;
    const int mbase=(warp>>2)*64, nbase=(warp&3)*32;
    const int bm=blockIdx.y*128, bn=blockIdx.x*128;
    const float* Asrc = SCATTER ? A : (const float*)g_attn;
    const float* Ab = Asrc + (size_t)bm*DIMC;
    const float* Bb = B + bn;

    float4 ar[2], br[2];
    float acc[4][4][4];
    #pragma unroll
    for(int i=0;i<4;i++)
      #pragma unroll
      for(int j=0;j<4;j++)
        #pragma unroll
        for(int k=0;k<4;k++) acc[i][j][k]=0.f;

    const int NT = DIMC/16;

    // prologue load tile 0
    #pragma unroll
    for(int i=0;i<2;i++){
        int idx=tid+(i<<8);
        ar[i]=*(const float4*)(Ab + (size_t)(idx>>2)*DIMC + ((idx&3)<<2));
        br[i]=*(const float4*)(Bb + (size_t)(idx>>5)*N + ((idx&31)<<2));
    }
    #pragma unroll
    for(int i=0;i<2;i++){
        int idx=tid+(i<<8);
        int r=idx>>2, kc=(idx&3)<<2;
        As[0][(kc+0)*ASTR+r]=f2tf(ar[i].x);
        As[0][(kc+1)*ASTR+r]=f2tf(ar[i].y);
        As[0][(kc+2)*ASTR+r]=f2tf(ar[i].z);
        As[0][(kc+3)*ASTR+r]=f2tf(ar[i].w);
        int rb=idx>>5, cb=(idx&31)<<2;
        unsigned* p=&Bs[0][rb*BSTR+cb];
        p[0]=f2tf(br[i].x); p[1]=f2tf(br[i].y); p[2]=f2tf(br[i].z); p[3]=f2tf(br[i].w);
    }
    __syncthreads();

    for(int kt=0;kt<NT;kt++){
        const int buf=kt&1;
        if(kt<NT-1){
            #pragma unroll
            for(int i=0;i<2;i++){
                int idx=tid+(i<<8);
                ar[i]=*(const float4*)(Ab + (size_t)(idx>>2)*DIMC + (kt+1)*16 + ((idx&3)<<2));
                br[i]=*(const float4*)(Bb + (size_t)((kt+1)*16+(idx>>5))*N + ((idx&31)<<2));
            }
        }
        #pragma unroll
        for(int ks=0;ks<2;ks++){
            const int k0=ks*8;
            unsigned af[4][4], bf[4][2];
            #pragma unroll
            for(int mi=0;mi<4;mi++){
                const int m0=mbase+mi*16;
                af[mi][0]=As[buf][(k0+tg)*ASTR+m0+g];
                af[mi][1]=As[buf][(k0+tg)*ASTR+m0+g+8];
                af[mi][2]=As[buf][(k0+tg+4)*ASTR+m0+g];
                af[mi][3]=As[buf][(k0+tg+4)*ASTR+m0+g+8];
            }
            #pragma unroll
            for(int ni=0;ni<4;ni++){
                const int n0=nbase+ni*8;
                bf[ni][0]=Bs[buf][(k0+tg)*BSTR+n0+g];
                bf[ni][1]=Bs[buf][(k0+tg+4)*BSTR+n0+g];
            }
            #pragma unroll
            for(int mi=0;mi<4;mi++)
                #pragma unroll
                for(int ni=0;ni<4;ni++)
                    mma8(acc[mi][ni],af[mi],bf[ni]);
        }
        if(kt<NT-1){
            #pragma unroll
            for(int i=0;i<2;i++){
                int idx=tid+(i<<8);
                int r=idx>>2, kc=(idx&3)<<2;
                As[buf^1][(kc+0)*ASTR+r]=f2tf(ar[i].x);
                As[buf^1][(kc+1)*ASTR+r]=f2tf(ar[i].y);
                As[buf^1][(kc+2)*ASTR+r]=f2tf(ar[i].z);
                As[buf^1][(kc+3)*ASTR+r]=f2tf(ar[i].w);
                int rb=idx>>5, cb=(idx&31)<<2;
                unsigned* p=&Bs[buf^1][rb*BSTR+cb];
                p[0]=f2tf(br[i].x); p[1]=f2tf(br[i].y); p[2]=f2tf(br[i].z); p[3]=f2tf(br[i].w);
            }
        }
        __syncthreads();
    }

    #pragma unroll
    for(int mi=0;mi<4;mi++){
        #pragma unroll
        for(int ni=0;ni<4;ni++){
            #pragma unroll
            for(int e=0;e<4;e++){
                const int r = bm + mbase + mi*16 + g + ((e>=2)?8:0);
                const int c = bn + nbase + ni*8 + 2*tg + (e&1);
                const float v = acc[mi][ni][e] + bias[c];
                if(SCATTER){
                    const int b=r>>11, s=r&2047;
                    const int t=c>>10, h=(c>>6)&15, d=c&63;
                    g_qkv[((((size_t)t*BATCH+b)*NHEAD+h)*SEQ+s)*HDIM+d]=v;
                } else {
                    out[(size_t)r*N+c]=v;
                }
            }
        }
    }
}

// ---------------------------------------------------------------------------
// Flash attention, tensor-core. 64-q tile per block, 4 warps x 16 q-rows.
// Smem stride 68 (bank = 4*row+col -> conflict-free fragment loads, no
// physical transposes: S uses K as [s][d], PV uses V as [s][d]).
// ---------------------------------------------------------------------------
#define QKOFF ((size_t)BATCH*NHEAD*SEQ*HDIM)
#define FSTR 68

__global__ __launch_bounds__(128)
void flash_mma()
{
    extern __shared__ unsigned sm[];
    unsigned* Qs=sm;
    unsigned* Ks=Qs+64*FSTR;
    unsigned* Vs=Ks+64*FSTR;
    unsigned* Ps=Vs+64*FSTR;
    const int tid=threadIdx.x, lane=tid&31, warp=tid>>5;
    const int g=lane>>2, tg=lane&3;
    const int qb=warp*16;
    const int b=blockIdx.y>>4, h=blockIdx.y&15;
    const int q0=blockIdx.x*64;
    const float* Qg=g_qkv + ((size_t)(b*NHEAD+h))*SEQ*HDIM;
    const float* Kg=Qg + QKOFF;
    const float* Vg=Kg + QKOFF;

    #pragma unroll
    for(int i=0;i<8;i++){
        int idx=tid+(i<<7);
        int r=idx>>4, c=(idx&15)<<2;
        float4 q4=*(const float4*)(Qg+(size_t)(q0+r)*HDIM+c);
        unsigned* p=&Qs[r*FSTR+c];
        p[0]=f2tf(q4.x); p[1]=f2tf(q4.y); p[2]=f2tf(q4.z); p[3]=f2tf(q4.w);
    }

    float oc[8][4];
    #pragma unroll
    for(int i=0;i<8;i++)
        #pragma unroll
        for(int j=0;j<4;j++) oc[i][j]=0.f;
    float m0=-1e30f, m1=-1e30f, l0=0.f, l1=0.f;
    const float scale=0.125f;

    for(int kt=0;kt<SEQ/64;kt++){
        __syncthreads();   // prev iteration done with Ks/Vs (covers Qs on iter 0)
        #pragma unroll
        for(int i=0;i<8;i++){
            int idx=tid+(i<<7);
            int r=idx>>4, c=(idx&15)<<2;
            float4 k4=*(const float4*)(Kg+(size_t)(kt*64+r)*HDIM+c);
            float4 v4=*(const float4*)(Vg+(size_t)(kt*64+r)*HDIM+c);
            unsigned* pk=&Ks[r*FSTR+c];
            pk[0]=f2tf(k4.x); pk[1]=f2tf(k4.y); pk[2]=f2tf(k4.z); pk[3]=f2tf(k4.w);
            unsigned* pv=&Vs[r*FSTR+c];
            pv[0]=f2tf(v4.x); pv[1]=f2tf(v4.y); pv[2]=f2tf(v4.z); pv[3]=f2tf(v4.w);
        }
        __syncthreads();

        // S = Q @ K^T : warp computes rows [qb, qb+16), all 64 keys
        float sc[8][4];
        #pragma unroll
        for(int i=0;i<8;i++)
            #pragma unroll
            for(int j=0;j<4;j++) sc[i][j]=0.f;
        #pragma unroll
        for(int ks=0;ks<8;ks++){
            const int k0=ks*8;
            unsigned af[4];
            af[0]=Qs[(qb+g  )*FSTR+k0+tg];
            af[1]=Qs[(qb+g+8)*FSTR+k0+tg];
            af[2]=Qs[(qb+g  )*FSTR+k0+tg+4];
            af[3]=Qs[(qb+g+8)*FSTR+k0+tg+4];
            #pragma unroll
            for(int ni=0;ni<8;ni++){
                unsigned bf[2];
                bf[0]=Ks[(ni*8+g)*FSTR+k0+tg];
                bf[1]=Ks[(ni*8+g)*FSTR+k0+tg+4];
                mma8(sc[ni],af,bf);
            }
        }

        // online softmax (rows g and g+8; col lanes = tig group, xor 1,2)
        float mx0=-1e30f, mx1=-1e30f;
        #pragma unroll
        for(int ni=0;ni<8;ni++){
            sc[ni][0]*=scale; sc[ni][1]*=scale; sc[ni][2]*=scale; sc[ni][3]*=scale;
            mx0=fmaxf(mx0,fmaxf(sc[ni][0],sc[ni][1]));
            mx1=fmaxf(mx1,fmaxf(sc[ni][2],sc[ni][3]));
        }
        mx0=fmaxf(mx0,__shfl_xor_sync(0xffffffffu,mx0,1));
        mx0=fmaxf(mx0,__shfl_xor_sync(0xffffffffu,mx0,2));
        mx1=fmaxf(mx1,__shfl_xor_sync(0xffffffffu,mx1,1));
        mx1=fmaxf(mx1,__shfl_xor_sync(0xffffffffu,mx1,2));
        const float nm0=fmaxf(m0,mx0), nm1=fmaxf(m1,mx1);
        const float a0=__expf(m0-nm0), a1=__expf(m1-nm1);
        m0=nm0; m1=nm1;
        float s0=0.f, s1=0.f;
        #pragma unroll
        for(int ni=0;ni<8;ni++){
            sc[ni][0]=__expf(sc[ni][0]-nm0); sc[ni][1]=__expf(sc[ni][1]-nm0);
            sc[ni][2]=__expf(sc[ni][2]-nm1); sc[ni][3]=__expf(sc[ni][3]-nm1);
            s0+=sc[ni][0]+sc[ni][1];
            s1+=sc[ni][2]+sc[ni][3];
        }
        s0+=__shfl_xor_sync(0xffffffffu,s0,1); s0+=__shfl_xor_sync(0xffffffffu,s0,2);
        s1+=__shfl_xor_sync(0xffffffffu,s1,1); s1+=__shfl_xor_sync(0xffffffffu,s1,2);
        l0=l0*a0+s0; l1=l1*a1+s1;

        // P -> smem (per-warp region, warp-local reuse)
        #pragma unroll
        for(int ni=0;ni<8;ni++){
            Ps[(qb+g  )*FSTR+ni*8+2*tg  ]=f2tf(sc[ni][0]);
            Ps[(qb+g  )*FSTR+ni*8+2*tg+1]=f2tf(sc[ni][1]);
            Ps[(qb+g+8)*FSTR+ni*8+2*tg  ]=f2tf(sc[ni][2]);
            Ps[(qb+g+8)*FSTR+ni*8+2*tg+1]=f2tf(sc[ni][3]);
        }
        __syncwarp();

        #pragma unroll
        for(int di=0;di<8;di++){
            oc[di][0]*=a0; oc[di][1]*=a0; oc[di][2]*=a1; oc[di][3]*=a1;
        }
        // O += P @ V
        #pragma unroll
        for(int ks=0;ks<8;ks++){
            const int k0=ks*8;
            unsigned af[4];
            af[0]=Ps[(qb+g  )*FSTR+k0+tg];
            af[1]=Ps[(qb+g+8)*FSTR+k0+tg];
            af[2]=Ps[(qb+g  )*FSTR+k0+tg+4];
            af[3]=Ps[(qb+g+8)*FSTR+k0+tg+4];
            #pragma unroll
            for(int di=0;di<8;di++){
                unsigned bf[2];
                bf[0]=Vs[(k0+tg  )*FSTR+di*8+g];
                bf[1]=Vs[(k0+tg+4)*FSTR+di*8+g];
                mma8(oc[di],af,bf);
            }
        }
    }

    const float i0=1.f/l0, i1=1.f/l1;
    const int r0=q0+qb+g, r1=r0+8;
    float* O0=&g_attn[((size_t)(b*SEQ)+r0)*DIMC + h*HDIM];
    float* O1=&g_attn[((size_t)(b*SEQ)+r1)*DIMC + h*HDIM];
    #pragma unroll
    for(int di=0;di<8;di++){
        const int c=di*8+2*tg;
        *(float2*)&O0[c]=make_float2(oc[di][0]*i0, oc[di][1]*i0);
        *(float2*)&O1[c]=make_float2(oc[di][2]*i1, oc[di][3]*i1);
    }
}

// ---------------------------------------------------------------------------
extern "C" void kernel_launch(void* const* d_in, const int* in_sizes, int n_in,
                              void* d_out, int out_size)
{
    const float* x     = (const float*)d_in[0];
    const float* Wqkv  = (const float*)d_in[1];
    const float* bqkv  = (const float*)d_in[2];
    const float* Wproj = (const float*)d_in[3];
    const float* bproj = (const float*)d_in[4];
    float* out = (float*)d_out;

    const int flash_smem = 4*64*FSTR*4;   // 69632 B
    cudaFuncSetAttribute(flash_mma, cudaFuncAttributeMaxDynamicSharedMemorySize, flash_smem);

    dim3 g1(NQKV/128, MTOT/128);   // (24, 64)
    gemm_mma<NQKV, true><<<g1, 256>>>(x, Wqkv, bqkv, nullptr);

    dim3 g2(SEQ/64, BATCH*NHEAD);  // (32, 64)
    flash_mma<<<g2, 128, flash_smem>>>();

    dim3 g3(DIMC/128, MTOT/128);   // (8, 64)
    gemm_mma<DIMC, false><<<g3, 256>>>(nullptr, Wproj, bproj, out);
}